// round 3
// baseline (speedup 1.0000x reference)
#include <cuda_runtime.h>
#include <cstdint>

// Scratch: per-segment counts (num_segments = out_size/64 <= 131072 assumed).
__device__ float g_counts[131072];

// ---------------------------------------------------------------------------
// Kernel 1: zero output sums + counts
// ---------------------------------------------------------------------------
__global__ void zero_kernel(float4* __restrict__ out4, int n4, int n_seg) {
    int i = blockIdx.x * blockDim.x + threadIdx.x;
    if (i < n4) out4[i] = make_float4(0.f, 0.f, 0.f, 0.f);
    if (i < n_seg) g_counts[i] = 0.f;
}

// ---------------------------------------------------------------------------
// Kernel 2: scatter-add. 16 threads cooperate on one row (64 floats = 16 x float4).
// Each thread: one coalesced float4 load of x, one red.global.add.v4.f32 into
// the segment accumulator. Group-leader adds 1.0 to the segment count.
// ---------------------------------------------------------------------------
__global__ void scatter_kernel(const float4* __restrict__ x4,
                               const int* __restrict__ index,   // int32 (JAX x64 disabled)
                               float* __restrict__ out,
                               int n_rows) {
    int gid = blockIdx.x * blockDim.x + threadIdx.x;
    int row  = gid >> 4;
    int lane = gid & 15;
    if (row >= n_rows) return;

    // All 16 lanes load the same address -> single sector, HW broadcast.
    int seg = index[row];

    float4 v = x4[(size_t)row * 16 + lane];

    float* dst = out + (size_t)seg * 64 + lane * 4;
    asm volatile("red.global.add.v4.f32 [%0], {%1, %2, %3, %4};"
                 :: "l"(dst), "f"(v.x), "f"(v.y), "f"(v.z), "f"(v.w)
                 : "memory");

    if (lane == 0) {
        float* cptr = &g_counts[seg];
        asm volatile("red.global.add.f32 [%0], %1;"
                     :: "l"(cptr), "f"(1.0f)
                     : "memory");
    }
}

// ---------------------------------------------------------------------------
// Kernel 3: divide each segment row by max(count, 1)
// ---------------------------------------------------------------------------
__global__ void finalize_kernel(float4* __restrict__ out4, int n_seg) {
    int i = blockIdx.x * blockDim.x + threadIdx.x;   // one float4 per thread
    int total = n_seg * 16;                          // 16 float4 per segment
    if (i >= total) return;
    float c = g_counts[i >> 4];
    float inv = 1.0f / fmaxf(c, 1.0f);
    float4 v = out4[i];
    v.x *= inv; v.y *= inv; v.z *= inv; v.w *= inv;
    out4[i] = v;
}

// ---------------------------------------------------------------------------
extern "C" void kernel_launch(void* const* d_in, const int* in_sizes, int n_in,
                              void* d_out, int out_size) {
    const float4* x4    = (const float4*)d_in[0];
    const int*    index = (const int*)d_in[1];
    float*        out   = (float*)d_out;

    int n_rows = in_sizes[1];        // len(index) == N
    int n_seg  = out_size / 64;      // D = 64
    int n4     = out_size / 4;

    {
        int threads = 256;
        int n = (n4 > n_seg) ? n4 : n_seg;
        int blocks = (n + threads - 1) / threads;
        zero_kernel<<<blocks, threads>>>((float4*)d_out, n4, n_seg);
    }
    {
        int threads = 256;
        long long total = (long long)n_rows * 16;
        int blocks = (int)((total + threads - 1) / threads);
        scatter_kernel<<<blocks, threads>>>(x4, index, out, n_rows);
    }
    {
        int threads = 256;
        int total = n_seg * 16;
        int blocks = (total + threads - 1) / threads;
        finalize_kernel<<<blocks, threads>>>((float4*)d_out, n_seg);
    }
}